// round 1
// baseline (speedup 1.0000x reference)
#include <cuda_runtime.h>
#include <cstdint>
#include <cstdio>

#define Bb 8
#define Tt 4096
#define Cc 1024
#define NELEM (8u*4096u*1024u)   // 33554432 per buffer

// One big scratch: [xk, xv, xr, k, v] each NELEM floats (671 MB total)
__device__ float g_scratch[5ull * NELEM];

// ---------------------------------------------------------------------------
// Mix kernel: time-shift + lerp, vectorized float4
// ---------------------------------------------------------------------------
__global__ void mix_kernel(const float4* __restrict__ x4,
                           const float4* __restrict__ tmk4,
                           const float4* __restrict__ tmv4,
                           const float4* __restrict__ tmr4,
                           float4* __restrict__ xk4,
                           float4* __restrict__ xv4,
                           float4* __restrict__ xr4) {
    int i = blockIdx.x * blockDim.x + threadIdx.x;   // 0 .. B*T*C/4-1
    int c4 = i & (Cc/4 - 1);
    int bt = i >> 8;              // C/4 = 256
    int t  = bt & (Tt - 1);
    float4 xc = x4[i];
    float4 xp = make_float4(0.f, 0.f, 0.f, 0.f);
    if (t != 0) xp = x4[i - Cc/4];
    float4 mk = tmk4[c4], mv = tmv4[c4], mr = tmr4[c4];
    float4 ok, ov, orr;
    ok.x = xc.x*mk.x + xp.x*(1.f-mk.x); ok.y = xc.y*mk.y + xp.y*(1.f-mk.y);
    ok.z = xc.z*mk.z + xp.z*(1.f-mk.z); ok.w = xc.w*mk.w + xp.w*(1.f-mk.w);
    ov.x = xc.x*mv.x + xp.x*(1.f-mv.x); ov.y = xc.y*mv.y + xp.y*(1.f-mv.y);
    ov.z = xc.z*mv.z + xp.z*(1.f-mv.z); ov.w = xc.w*mv.w + xp.w*(1.f-mv.w);
    orr.x = xc.x*mr.x + xp.x*(1.f-mr.x); orr.y = xc.y*mr.y + xp.y*(1.f-mr.y);
    orr.z = xc.z*mr.z + xp.z*(1.f-mr.z); orr.w = xc.w*mr.w + xp.w*(1.f-mr.w);
    xk4[i] = ok; xv4[i] = ov; xr4[i] = orr;
}

// ---------------------------------------------------------------------------
// TF32 GEMM: Out[m,n] = sum_k A[m,k] * W[n,k]   (A: [32768,1024], W: [1024,1024])
// Tile: BM=128, BN=64, BK=32, 256 threads (8 warps, 4x2 warp grid, 32x32/warp)
// EPI: 0 = identity, 1 = sigmoid
// ---------------------------------------------------------------------------
__device__ __forceinline__ uint32_t f2tf32(float x) {
    uint32_t r;
    asm("cvt.rna.tf32.f32 %0, %1;" : "=r"(r) : "f"(x));
    return r;
}

__device__ __forceinline__ void mma_tf32(float c[4], const uint32_t a[4], const uint32_t b[2]) {
    asm volatile(
        "mma.sync.aligned.m16n8k8.row.col.f32.tf32.tf32.f32 "
        "{%0,%1,%2,%3}, {%4,%5,%6,%7}, {%8,%9}, {%0,%1,%2,%3};\n"
        : "+f"(c[0]), "+f"(c[1]), "+f"(c[2]), "+f"(c[3])
        : "r"(a[0]), "r"(a[1]), "r"(a[2]), "r"(a[3]), "r"(b[0]), "r"(b[1]));
}

#define BM 128
#define BN 64
#define BK 32
#define BKP 36   // padded pitch: bank = (4*row + col) & 31 -> conflict-free frag loads

template <int EPI>
__global__ __launch_bounds__(256)
void gemm_kernel(const float* __restrict__ A, const float* __restrict__ W,
                 float* __restrict__ Out) {
    __shared__ float As[BM * BKP];
    __shared__ float Bs[BN * BKP];

    const int tid  = threadIdx.x;
    const int bm   = blockIdx.y;
    const int bn   = blockIdx.x;
    const int warp = tid >> 5, lane = tid & 31;
    const int wM = warp >> 1, wN = warp & 1;
    const int grp = lane >> 2, qd = lane & 3;

    const float* Ablk = A + (size_t)bm * BM * Cc;
    const float* Wblk = W + (size_t)bn * BN * Cc;

    const int rA = tid >> 3;           // 0..31
    const int c4 = (tid & 7) * 4;      // 0,4,..,28

    float acc[2][4][4];
    #pragma unroll
    for (int mt = 0; mt < 2; mt++)
        #pragma unroll
        for (int nt = 0; nt < 4; nt++)
            #pragma unroll
            for (int j = 0; j < 4; j++) acc[mt][nt][j] = 0.f;

    for (int k0 = 0; k0 < Cc; k0 += BK) {
        #pragma unroll
        for (int i = 0; i < 4; i++) {
            float4 v = *(const float4*)(Ablk + (size_t)(rA + 32*i) * Cc + k0 + c4);
            *(float4*)&As[(rA + 32*i) * BKP + c4] = v;
        }
        #pragma unroll
        for (int i = 0; i < 2; i++) {
            float4 v = *(const float4*)(Wblk + (size_t)(rA + 32*i) * Cc + k0 + c4);
            *(float4*)&Bs[(rA + 32*i) * BKP + c4] = v;
        }
        __syncthreads();

        #pragma unroll
        for (int ks = 0; ks < 4; ks++) {
            const int kb = ks * 8;
            uint32_t af[2][4], bf[4][2];
            #pragma unroll
            for (int mt = 0; mt < 2; mt++) {
                int r0 = wM * 32 + mt * 16 + grp;
                af[mt][0] = f2tf32(As[r0       * BKP + kb + qd]);
                af[mt][1] = f2tf32(As[(r0 + 8) * BKP + kb + qd]);
                af[mt][2] = f2tf32(As[r0       * BKP + kb + qd + 4]);
                af[mt][3] = f2tf32(As[(r0 + 8) * BKP + kb + qd + 4]);
            }
            #pragma unroll
            for (int nt = 0; nt < 4; nt++) {
                int n0 = wN * 32 + nt * 8 + grp;
                bf[nt][0] = f2tf32(Bs[n0 * BKP + kb + qd]);
                bf[nt][1] = f2tf32(Bs[n0 * BKP + kb + qd + 4]);
            }
            #pragma unroll
            for (int mt = 0; mt < 2; mt++)
                #pragma unroll
                for (int nt = 0; nt < 4; nt++)
                    mma_tf32(acc[mt][nt], af[mt], bf[nt]);
        }
        __syncthreads();
    }

    // Epilogue
    #pragma unroll
    for (int mt = 0; mt < 2; mt++) {
        #pragma unroll
        for (int nt = 0; nt < 4; nt++) {
            int m0 = bm * BM + wM * 32 + mt * 16 + grp;
            int n0 = bn * BN + wN * 32 + nt * 8 + qd * 2;
            float v0 = acc[mt][nt][0], v1 = acc[mt][nt][1];
            float v2 = acc[mt][nt][2], v3 = acc[mt][nt][3];
            if (EPI == 1) {
                v0 = 1.f / (1.f + __expf(-v0));
                v1 = 1.f / (1.f + __expf(-v1));
                v2 = 1.f / (1.f + __expf(-v2));
                v3 = 1.f / (1.f + __expf(-v3));
            }
            *(float2*)&Out[(size_t)m0 * Cc + n0]       = make_float2(v0, v1);
            *(float2*)&Out[(size_t)(m0 + 8) * Cc + n0] = make_float2(v2, v3);
        }
    }
}

// ---------------------------------------------------------------------------
// WKV scan: one thread per (b,c) channel, serial over T.
// Fuses r*y into output.
// ---------------------------------------------------------------------------
__global__ void wkv_kernel(const float* __restrict__ K, const float* __restrict__ V,
                           const float* __restrict__ R, float* __restrict__ RY,
                           const float* __restrict__ time_decay,
                           const float* __restrict__ time_first) {
    int idx = blockIdx.x * blockDim.x + threadIdx.x;   // 0..B*C-1
    int b = idx >> 10;
    int c = idx & (Cc - 1);
    float w = -__expf(time_decay[c]);
    float u = time_first[c];

    float aa = 0.f, bb = 0.f, pp = -1e30f;
    size_t base = (size_t)b * Tt * Cc + c;

    for (int t = 0; t < Tt; t++) {
        size_t off = base + (size_t)t * Cc;
        float kt = K[off];
        float vt = V[off];

        float ww = u + pp;
        float p  = fmaxf(ww, kt);
        float e1 = __expf(ww - p);
        float e2 = __expf(kt - p);
        float y  = (aa * e1 + vt * e2) / (bb * e1 + e2 + 1e-6f);
        RY[off] = y * R[off];

        float ww2 = w + pp;
        float p2  = fmaxf(ww2, kt);
        float e1b = __expf(ww2 - p2);
        float e2b = __expf(kt - p2);
        aa = aa * e1b + vt * e2b;
        bb = bb * e1b + e2b;
        pp = p2;
    }
}

// ---------------------------------------------------------------------------
// Launch
// ---------------------------------------------------------------------------
extern "C" void kernel_launch(void* const* d_in, const int* in_sizes, int n_in,
                              void* d_out, int out_size) {
    const float* x          = (const float*)d_in[0];
    const float* time_decay = (const float*)d_in[1];
    const float* time_first = (const float*)d_in[2];
    const float* tmk        = (const float*)d_in[3];
    const float* tmv        = (const float*)d_in[4];
    const float* tmr        = (const float*)d_in[5];
    const float* Wk         = (const float*)d_in[6];
    const float* Wv         = (const float*)d_in[7];
    const float* Wr         = (const float*)d_in[8];
    const float* Wo         = (const float*)d_in[9];
    float* out = (float*)d_out;

    float* scratch = nullptr;
    cudaGetSymbolAddress((void**)&scratch, g_scratch);
    float* g_xk = scratch + 0ull * NELEM;
    float* g_xv = scratch + 1ull * NELEM;
    float* g_xr = scratch + 2ull * NELEM;
    float* g_k  = scratch + 3ull * NELEM;
    float* g_v  = scratch + 4ull * NELEM;

    // 1. mix
    {
        int total4 = Bb * Tt * Cc / 4;
        mix_kernel<<<total4 / 256, 256>>>((const float4*)x,
                                          (const float4*)tmk, (const float4*)tmv,
                                          (const float4*)tmr,
                                          (float4*)g_xk, (float4*)g_xv, (float4*)g_xr);
    }

    dim3 grid(Cc / BN, (Bb * Tt) / BM);   // (16, 256)

    // 2. k = xk @ Wk^T
    gemm_kernel<0><<<grid, 256>>>(g_xk, Wk, g_k);
    // 3. v = xv @ Wv^T
    gemm_kernel<0><<<grid, 256>>>(g_xv, Wv, g_v);
    // 4. r = sigmoid(xr @ Wr^T)  -> reuse g_xk
    gemm_kernel<1><<<grid, 256>>>(g_xr, Wr, g_xk);
    // 5. wkv scan, ry -> reuse g_xv
    wkv_kernel<<<(Bb * Cc) / 64, 64>>>(g_k, g_v, g_xk, g_xv, time_decay, time_first);
    // 6. out = ry @ Wo^T
    gemm_kernel<0><<<grid, 256>>>(g_xv, Wo, out);
}

// round 2
// speedup vs baseline: 2.1981x; 2.1981x over previous
#include <cuda_runtime.h>
#include <cstdint>

#define Bb 8
#define Tt 4096
#define Cc 1024
#define NELEM (8u*4096u*1024u)   // 33554432 per buffer
#define NCH 32
#define CHL 128                  // Tt / NCH
#define BC  (Bb*Cc)              // 8192

// Scratch: [xk, xv, xr, k, v] each NELEM floats
__device__ float g_scratch[5ull * NELEM];
// WKV states: local (aa,bb,pp) and incoming (aa,bb,pp), each BC*NCH floats
__device__ float g_state[6ull * BC * NCH];

// ---------------------------------------------------------------------------
// Mix kernel: time-shift + lerp, vectorized float4
// ---------------------------------------------------------------------------
__global__ void mix_kernel(const float4* __restrict__ x4,
                           const float4* __restrict__ tmk4,
                           const float4* __restrict__ tmv4,
                           const float4* __restrict__ tmr4,
                           float4* __restrict__ xk4,
                           float4* __restrict__ xv4,
                           float4* __restrict__ xr4) {
    int i = blockIdx.x * blockDim.x + threadIdx.x;
    int c4 = i & (Cc/4 - 1);
    int bt = i >> 8;
    int t  = bt & (Tt - 1);
    float4 xc = x4[i];
    float4 xp = make_float4(0.f, 0.f, 0.f, 0.f);
    if (t != 0) xp = x4[i - Cc/4];
    float4 mk = tmk4[c4], mv = tmv4[c4], mr = tmr4[c4];
    float4 ok, ov, orr;
    ok.x = xc.x*mk.x + xp.x*(1.f-mk.x); ok.y = xc.y*mk.y + xp.y*(1.f-mk.y);
    ok.z = xc.z*mk.z + xp.z*(1.f-mk.z); ok.w = xc.w*mk.w + xp.w*(1.f-mk.w);
    ov.x = xc.x*mv.x + xp.x*(1.f-mv.x); ov.y = xc.y*mv.y + xp.y*(1.f-mv.y);
    ov.z = xc.z*mv.z + xp.z*(1.f-mv.z); ov.w = xc.w*mv.w + xp.w*(1.f-mv.w);
    orr.x = xc.x*mr.x + xp.x*(1.f-mr.x); orr.y = xc.y*mr.y + xp.y*(1.f-mr.y);
    orr.z = xc.z*mr.z + xp.z*(1.f-mr.z); orr.w = xc.w*mr.w + xp.w*(1.f-mr.w);
    xk4[i] = ok; xv4[i] = ov; xr4[i] = orr;
}

// ---------------------------------------------------------------------------
// TF32 GEMM: Out[m,n] = sum_k A[m,k]*W[n,k]. Double-buffered smem,
// TF32 conversion at smem-store time, one bar.sync per k-iter.
// ---------------------------------------------------------------------------
__device__ __forceinline__ uint32_t f2tf32(float x) {
    uint32_t r;
    asm("cvt.rna.tf32.f32 %0, %1;" : "=r"(r) : "f"(x));
    return r;
}

__device__ __forceinline__ void mma_tf32(float c[4], const uint32_t a[4], const uint32_t b[2]) {
    asm volatile(
        "mma.sync.aligned.m16n8k8.row.col.f32.tf32.tf32.f32 "
        "{%0,%1,%2,%3}, {%4,%5,%6,%7}, {%8,%9}, {%0,%1,%2,%3};\n"
        : "+f"(c[0]), "+f"(c[1]), "+f"(c[2]), "+f"(c[3])
        : "r"(a[0]), "r"(a[1]), "r"(a[2]), "r"(a[3]), "r"(b[0]), "r"(b[1]));
}

#define BM 128
#define BN 64
#define BK 32
#define BKP 36   // pitch: bank = (4*row + col) & 31 -> conflict-free frag loads
#define GEMM_SMEM (2 * (BM + BN) * BKP * 4)

template <int EPI>
__global__ __launch_bounds__(256)
void gemm_kernel(const float* __restrict__ A, const float* __restrict__ W,
                 float* __restrict__ Out) {
    extern __shared__ uint32_t sm[];
    uint32_t* AsBase = sm;                      // 2 * BM*BKP
    uint32_t* BsBase = sm + 2 * BM * BKP;       // 2 * BN*BKP

    const int tid  = threadIdx.x;
    const int bm   = blockIdx.y;
    const int bn   = blockIdx.x;
    const int warp = tid >> 5, lane = tid & 31;
    const int wM = warp >> 1, wN = warp & 1;
    const int grp = lane >> 2, qd = lane & 3;

    const float* Ablk = A + (size_t)bm * BM * Cc;
    const float* Wblk = W + (size_t)bn * BN * Cc;

    const int rA = tid >> 3;           // 0..31
    const int c4 = (tid & 7) * 4;      // 0,4,..,28

    float acc[2][4][4];
    #pragma unroll
    for (int mt = 0; mt < 2; mt++)
        #pragma unroll
        for (int nt = 0; nt < 4; nt++)
            #pragma unroll
            for (int j = 0; j < 4; j++) acc[mt][nt][j] = 0.f;

    float4 ra[4], rb[2];

    // preload tile 0 into registers
    #pragma unroll
    for (int i = 0; i < 4; i++)
        ra[i] = *(const float4*)(Ablk + (size_t)(rA + 32*i) * Cc + c4);
    #pragma unroll
    for (int i = 0; i < 2; i++)
        rb[i] = *(const float4*)(Wblk + (size_t)(rA + 32*i) * Cc + c4);

    // store (cvt to tf32) into buffer 0
    {
        uint32_t* Asb = AsBase;
        uint32_t* Bsb = BsBase;
        #pragma unroll
        for (int i = 0; i < 4; i++) {
            int row = rA + 32*i;
            Asb[row*BKP + c4 + 0] = f2tf32(ra[i].x);
            Asb[row*BKP + c4 + 1] = f2tf32(ra[i].y);
            Asb[row*BKP + c4 + 2] = f2tf32(ra[i].z);
            Asb[row*BKP + c4 + 3] = f2tf32(ra[i].w);
        }
        #pragma unroll
        for (int i = 0; i < 2; i++) {
            int row = rA + 32*i;
            Bsb[row*BKP + c4 + 0] = f2tf32(rb[i].x);
            Bsb[row*BKP + c4 + 1] = f2tf32(rb[i].y);
            Bsb[row*BKP + c4 + 2] = f2tf32(rb[i].z);
            Bsb[row*BKP + c4 + 3] = f2tf32(rb[i].w);
        }
    }
    __syncthreads();

    int cur = 0;
    for (int k0 = 0; k0 < Cc; k0 += BK) {
        const bool has_next = (k0 + BK) < Cc;
        if (has_next) {
            #pragma unroll
            for (int i = 0; i < 4; i++)
                ra[i] = *(const float4*)(Ablk + (size_t)(rA + 32*i) * Cc + k0 + BK + c4);
            #pragma unroll
            for (int i = 0; i < 2; i++)
                rb[i] = *(const float4*)(Wblk + (size_t)(rA + 32*i) * Cc + k0 + BK + c4);
        }

        const uint32_t* Asb = AsBase + cur * BM * BKP;
        const uint32_t* Bsb = BsBase + cur * BN * BKP;

        #pragma unroll
        for (int ks = 0; ks < 4; ks++) {
            const int kb = ks * 8;
            uint32_t af[2][4], bf[4][2];
            #pragma unroll
            for (int mt = 0; mt < 2; mt++) {
                int r0 = wM * 32 + mt * 16 + grp;
                af[mt][0] = Asb[r0       * BKP + kb + qd];
                af[mt][1] = Asb[(r0 + 8) * BKP + kb + qd];
                af[mt][2] = Asb[r0       * BKP + kb + qd + 4];
                af[mt][3] = Asb[(r0 + 8) * BKP + kb + qd + 4];
            }
            #pragma unroll
            for (int nt = 0; nt < 4; nt++) {
                int n0 = wN * 32 + nt * 8 + grp;
                bf[nt][0] = Bsb[n0 * BKP + kb + qd];
                bf[nt][1] = Bsb[n0 * BKP + kb + qd + 4];
            }
            #pragma unroll
            for (int mt = 0; mt < 2; mt++)
                #pragma unroll
                for (int nt = 0; nt < 4; nt++)
                    mma_tf32(acc[mt][nt], af[mt], bf[nt]);
        }

        if (has_next) {
            uint32_t* Asn = AsBase + (cur ^ 1) * BM * BKP;
            uint32_t* Bsn = BsBase + (cur ^ 1) * BN * BKP;
            #pragma unroll
            for (int i = 0; i < 4; i++) {
                int row = rA + 32*i;
                Asn[row*BKP + c4 + 0] = f2tf32(ra[i].x);
                Asn[row*BKP + c4 + 1] = f2tf32(ra[i].y);
                Asn[row*BKP + c4 + 2] = f2tf32(ra[i].z);
                Asn[row*BKP + c4 + 3] = f2tf32(ra[i].w);
            }
            #pragma unroll
            for (int i = 0; i < 2; i++) {
                int row = rA + 32*i;
                Bsn[row*BKP + c4 + 0] = f2tf32(rb[i].x);
                Bsn[row*BKP + c4 + 1] = f2tf32(rb[i].y);
                Bsn[row*BKP + c4 + 2] = f2tf32(rb[i].z);
                Bsn[row*BKP + c4 + 3] = f2tf32(rb[i].w);
            }
        }
        __syncthreads();
        cur ^= 1;
    }

    // Epilogue
    #pragma unroll
    for (int mt = 0; mt < 2; mt++) {
        #pragma unroll
        for (int nt = 0; nt < 4; nt++) {
            int m0 = bm * BM + wM * 32 + mt * 16 + grp;
            int n0 = bn * BN + wN * 32 + nt * 8 + qd * 2;
            float v0 = acc[mt][nt][0], v1 = acc[mt][nt][1];
            float v2 = acc[mt][nt][2], v3 = acc[mt][nt][3];
            if (EPI == 1) {
                v0 = 1.f / (1.f + __expf(-v0));
                v1 = 1.f / (1.f + __expf(-v1));
                v2 = 1.f / (1.f + __expf(-v2));
                v3 = 1.f / (1.f + __expf(-v3));
            }
            *(float2*)&Out[(size_t)m0 * Cc + n0]       = make_float2(v0, v1);
            *(float2*)&Out[(size_t)(m0 + 8) * Cc + n0] = make_float2(v2, v3);
        }
    }
}

// ---------------------------------------------------------------------------
// WKV chunk-parallel scan. State (aa,bb,pp) with A = aa*e^pp, B = bb*e^pp;
// pp is the running decayed max — composes exactly across chunks.
// ---------------------------------------------------------------------------
// Phase 1: per-chunk local state starting from (0,0,-1e30)
__global__ void wkv_phase1(const float* __restrict__ K, const float* __restrict__ V,
                           const float* __restrict__ time_decay,
                           float* __restrict__ st_aa, float* __restrict__ st_bb,
                           float* __restrict__ st_pp) {
    int idx = blockIdx.x * blockDim.x + threadIdx.x;   // 0..BC*NCH-1
    int bc = idx & (BC - 1);
    int ch = idx >> 13;                                 // BC = 8192 = 2^13
    int c  = bc & (Cc - 1);
    int b  = bc >> 10;
    float w = -__expf(time_decay[c]);

    float aa = 0.f, bb = 0.f, pp = -1e30f;
    size_t off = ((size_t)b * Tt + (size_t)ch * CHL) * Cc + c;
    for (int t = 0; t < CHL; t++) {
        float kt = K[off];
        float vt = V[off];
        float ww2 = w + pp;
        float p2  = fmaxf(ww2, kt);
        float e1b = __expf(ww2 - p2);
        float e2b = __expf(kt - p2);
        aa = aa * e1b + vt * e2b;
        bb = bb * e1b + e2b;
        pp = p2;
        off += Cc;
    }
    st_aa[idx] = aa; st_bb[idx] = bb; st_pp[idx] = pp;
}

// Phase 2: sequential combine over chunks -> incoming state per chunk
__global__ void wkv_phase2(const float* __restrict__ time_decay,
                           const float* __restrict__ st_aa, const float* __restrict__ st_bb,
                           const float* __restrict__ st_pp,
                           float* __restrict__ in_aa, float* __restrict__ in_bb,
                           float* __restrict__ in_pp) {
    int bc = blockIdx.x * blockDim.x + threadIdx.x;    // 0..BC-1
    int c  = bc & (Cc - 1);
    float w  = -__expf(time_decay[c]);
    float wL = w * (float)CHL;

    float aa = 0.f, bb = 0.f, pp = -1e30f;
    for (int ch = 0; ch < NCH; ch++) {
        int i = ch * BC + bc;
        in_aa[i] = aa; in_bb[i] = bb; in_pp[i] = pp;
        float la = st_aa[i], lb = st_bb[i], lp = st_pp[i];
        float pn   = fmaxf(pp + wL, lp);
        float e_in = __expf(pp + wL - pn);
        float e_lc = __expf(lp - pn);
        aa = aa * e_in + la * e_lc;
        bb = bb * e_in + lb * e_lc;
        pp = pn;
    }
}

// Phase 3: re-scan each chunk from its incoming state, emit r*y
__global__ void wkv_phase3(const float* __restrict__ K, const float* __restrict__ V,
                           const float* __restrict__ R, float* __restrict__ RY,
                           const float* __restrict__ time_decay,
                           const float* __restrict__ time_first,
                           const float* __restrict__ in_aa, const float* __restrict__ in_bb,
                           const float* __restrict__ in_pp) {
    int idx = blockIdx.x * blockDim.x + threadIdx.x;
    int bc = idx & (BC - 1);
    int ch = idx >> 13;
    int c  = bc & (Cc - 1);
    int b  = bc >> 10;
    float w = -__expf(time_decay[c]);
    float u = time_first[c];

    float aa = in_aa[idx], bb = in_bb[idx], pp = in_pp[idx];
    size_t off = ((size_t)b * Tt + (size_t)ch * CHL) * Cc + c;
    for (int t = 0; t < CHL; t++) {
        float kt = K[off];
        float vt = V[off];

        float ww = u + pp;
        float p  = fmaxf(ww, kt);
        float e1 = __expf(ww - p);
        float e2 = __expf(kt - p);
        float y  = (aa * e1 + vt * e2) / (bb * e1 + e2 + 1e-6f);
        RY[off] = y * R[off];

        float ww2 = w + pp;
        float p2  = fmaxf(ww2, kt);
        float e1b = __expf(ww2 - p2);
        float e2b = __expf(kt - p2);
        aa = aa * e1b + vt * e2b;
        bb = bb * e1b + e2b;
        pp = p2;
        off += Cc;
    }
}

// ---------------------------------------------------------------------------
// Launch
// ---------------------------------------------------------------------------
extern "C" void kernel_launch(void* const* d_in, const int* in_sizes, int n_in,
                              void* d_out, int out_size) {
    const float* x          = (const float*)d_in[0];
    const float* time_decay = (const float*)d_in[1];
    const float* time_first = (const float*)d_in[2];
    const float* tmk        = (const float*)d_in[3];
    const float* tmv        = (const float*)d_in[4];
    const float* tmr        = (const float*)d_in[5];
    const float* Wk         = (const float*)d_in[6];
    const float* Wv         = (const float*)d_in[7];
    const float* Wr         = (const float*)d_in[8];
    const float* Wo         = (const float*)d_in[9];
    float* out = (float*)d_out;

    float* scratch = nullptr;
    cudaGetSymbolAddress((void**)&scratch, g_scratch);
    float* g_xk = scratch + 0ull * NELEM;
    float* g_xv = scratch + 1ull * NELEM;
    float* g_xr = scratch + 2ull * NELEM;
    float* g_k  = scratch + 3ull * NELEM;
    float* g_v  = scratch + 4ull * NELEM;

    float* state = nullptr;
    cudaGetSymbolAddress((void**)&state, g_state);
    float* st_aa = state + 0ull * BC * NCH;
    float* st_bb = state + 1ull * BC * NCH;
    float* st_pp = state + 2ull * BC * NCH;
    float* in_aa = state + 3ull * BC * NCH;
    float* in_bb = state + 4ull * BC * NCH;
    float* in_pp = state + 5ull * BC * NCH;

    cudaFuncSetAttribute(gemm_kernel<0>, cudaFuncAttributeMaxDynamicSharedMemorySize, GEMM_SMEM);
    cudaFuncSetAttribute(gemm_kernel<1>, cudaFuncAttributeMaxDynamicSharedMemorySize, GEMM_SMEM);

    // 1. mix
    {
        int total4 = Bb * Tt * Cc / 4;
        mix_kernel<<<total4 / 256, 256>>>((const float4*)x,
                                          (const float4*)tmk, (const float4*)tmv,
                                          (const float4*)tmr,
                                          (float4*)g_xk, (float4*)g_xv, (float4*)g_xr);
    }

    dim3 grid(Cc / BN, (Bb * Tt) / BM);   // (16, 256)

    // 2-4. projections
    gemm_kernel<0><<<grid, 256, GEMM_SMEM>>>(g_xk, Wk, g_k);
    gemm_kernel<0><<<grid, 256, GEMM_SMEM>>>(g_xv, Wv, g_v);
    gemm_kernel<1><<<grid, 256, GEMM_SMEM>>>(g_xr, Wr, g_xk);  // r -> g_xk

    // 5. chunk-parallel WKV scan; ry -> g_xv
    wkv_phase1<<<(BC * NCH) / 256, 256>>>(g_k, g_v, time_decay, st_aa, st_bb, st_pp);
    wkv_phase2<<<BC / 256, 256>>>(time_decay, st_aa, st_bb, st_pp, in_aa, in_bb, in_pp);
    wkv_phase3<<<(BC * NCH) / 256, 256>>>(g_k, g_v, g_xk, g_xv, time_decay, time_first,
                                          in_aa, in_bb, in_pp);

    // 6. out = ry @ Wo^T
    gemm_kernel<0><<<grid, 256, GEMM_SMEM>>>(g_xv, Wo, out);
}

// round 4
// speedup vs baseline: 2.7414x; 1.2472x over previous
#include <cuda_runtime.h>
#include <cstdint>

#define Bb 8
#define Tt 4096
#define Cc 1024
#define NELEM (8u*4096u*1024u)
#define NCH 32
#define CHL 128
#define BC  (Bb*Cc)

__device__ float g_scratch[5ull * NELEM];
__device__ float g_state[6ull * BC * NCH];
__device__ float g_wr[4ull * 1024 * 1024];   // tf32-rounded weights

// ===========================================================================
// helpers
// ===========================================================================
__device__ __forceinline__ uint32_t smem_to_u32(const void* p) {
    uint32_t a;
    asm("{ .reg .u64 t; cvta.to.shared.u64 t, %1; cvt.u32.u64 %0, t; }"
        : "=r"(a) : "l"(p));
    return a;
}

__device__ __forceinline__ float rndtf32(float x) {
    uint32_t r;
    asm("cvt.rna.tf32.f32 %0, %1;" : "=r"(r) : "f"(x));
    return __uint_as_float(r);
}

__device__ __forceinline__ void mma_tf32(float c[4], const uint32_t a[4], const uint32_t b[2]) {
    asm volatile(
        "mma.sync.aligned.m16n8k8.row.col.f32.tf32.tf32.f32 "
        "{%0,%1,%2,%3}, {%4,%5,%6,%7}, {%8,%9}, {%0,%1,%2,%3};\n"
        : "+f"(c[0]), "+f"(c[1]), "+f"(c[2]), "+f"(c[3])
        : "r"(a[0]), "r"(a[1]), "r"(a[2]), "r"(a[3]), "r"(b[0]), "r"(b[1]));
}

__device__ __forceinline__ void cp_async16(uint32_t dst, const void* src) {
    asm volatile("cp.async.cg.shared.global [%0], [%1], 16;" :: "r"(dst), "l"(src));
}
#define CP_COMMIT() asm volatile("cp.async.commit_group;" ::: "memory")
#define CP_WAIT1()  asm volatile("cp.async.wait_group 1;" ::: "memory")
#define CP_WAIT0()  asm volatile("cp.async.wait_group 0;" ::: "memory")

// ===========================================================================
// round weights to tf32-representable fp32
// ===========================================================================
__global__ void round_tf32_kernel(const float4* __restrict__ in, float4* __restrict__ out, int n4) {
    int i = blockIdx.x * blockDim.x + threadIdx.x;
    if (i < n4) {
        float4 v = in[i];
        out[i] = make_float4(rndtf32(v.x), rndtf32(v.y), rndtf32(v.z), rndtf32(v.w));
    }
}

// ===========================================================================
// Mix kernel (outputs tf32-rounded so the GEMM can consume raw fp32 bits)
// ===========================================================================
__global__ void mix_kernel(const float4* __restrict__ x4,
                           const float4* __restrict__ tmk4,
                           const float4* __restrict__ tmv4,
                           const float4* __restrict__ tmr4,
                           float4* __restrict__ xk4,
                           float4* __restrict__ xv4,
                           float4* __restrict__ xr4) {
    int i = blockIdx.x * blockDim.x + threadIdx.x;
    int c4 = i & (Cc/4 - 1);
    int bt = i >> 8;
    int t  = bt & (Tt - 1);
    float4 xc = x4[i];
    float4 xp = make_float4(0.f, 0.f, 0.f, 0.f);
    if (t != 0) xp = x4[i - Cc/4];
    float4 mk = tmk4[c4], mv = tmv4[c4], mr = tmr4[c4];
    float4 ok, ov, orr;
    ok.x = rndtf32(xc.x*mk.x + xp.x*(1.f-mk.x)); ok.y = rndtf32(xc.y*mk.y + xp.y*(1.f-mk.y));
    ok.z = rndtf32(xc.z*mk.z + xp.z*(1.f-mk.z)); ok.w = rndtf32(xc.w*mk.w + xp.w*(1.f-mk.w));
    ov.x = rndtf32(xc.x*mv.x + xp.x*(1.f-mv.x)); ov.y = rndtf32(xc.y*mv.y + xp.y*(1.f-mv.y));
    ov.z = rndtf32(xc.z*mv.z + xp.z*(1.f-mv.z)); ov.w = rndtf32(xc.w*mv.w + xp.w*(1.f-mv.w));
    orr.x = rndtf32(xc.x*mr.x + xp.x*(1.f-mr.x)); orr.y = rndtf32(xc.y*mr.y + xp.y*(1.f-mr.y));
    orr.z = rndtf32(xc.z*mr.z + xp.z*(1.f-mr.z)); orr.w = rndtf32(xc.w*mr.w + xp.w*(1.f-mr.w));
    xk4[i] = ok; xv4[i] = ov; xr4[i] = orr;
}

// ===========================================================================
// TF32 GEMM: Out[m,n] = sum_k A[m,k]*W[n,k]
// CTA 128x128, 4 warps (warp tile 64x64), BK=32 floats, 3-stage cp.async.
// Inputs must already be tf32-rounded fp32.
// ===========================================================================
#define BM 128
#define BN 128
#define BKF 32
#define BKP 36     // padded pitch (floats): conflict-free fragment loads
#define NST 3
#define STAGE_FLOATS ((BM + BN) * BKP)      // 9216 floats = 36864 B
#define GEMM_SMEM (NST * STAGE_FLOATS * 4)  // 110592 B

__device__ __forceinline__ void gemm_issue_stage(
    const float* __restrict__ Ablk, const float* __restrict__ Wblk,
    uint32_t sbase, int s, int tid) {
    int buf = s % NST;
    uint32_t sA = sbase + (uint32_t)buf * (STAGE_FLOATS * 4);
    uint32_t sB = sA + BM * BKP * 4;
    int k0 = s * BKF;
    #pragma unroll
    for (int i = 0; i < 8; i++) {
        int idx = i * 128 + tid;
        int row = idx >> 3;
        int c4  = (idx & 7) * 4;
        cp_async16(sA + (uint32_t)(row * BKP + c4) * 4, Ablk + (size_t)row * Cc + k0 + c4);
        cp_async16(sB + (uint32_t)(row * BKP + c4) * 4, Wblk + (size_t)row * Cc + k0 + c4);
    }
    CP_COMMIT();
}

template <int EPI>
__global__ __launch_bounds__(128, 2)
void gemm_tc(const float* __restrict__ A, const float* __restrict__ W,
             float* __restrict__ Out) {
    extern __shared__ float smf[];
    const uint32_t sbase = smem_to_u32(smf);
    const int tid  = threadIdx.x;
    const int warp = tid >> 5, lane = tid & 31;
    const int wM = warp >> 1, wN = warp & 1;
    const int grp = lane >> 2, qd = lane & 3;
    const int bn = blockIdx.x, bm = blockIdx.y;

    const float* Ablk = A + (size_t)bm * BM * Cc;
    const float* Wblk = W + (size_t)bn * BN * Cc;

    float acc[4][8][4];
    #pragma unroll
    for (int mt = 0; mt < 4; mt++)
        #pragma unroll
        for (int nt = 0; nt < 8; nt++)
            #pragma unroll
            for (int j = 0; j < 4; j++) acc[mt][nt][j] = 0.f;

    gemm_issue_stage(Ablk, Wblk, sbase, 0, tid);
    gemm_issue_stage(Ablk, Wblk, sbase, 1, tid);

    const int NSTEP = Cc / BKF;   // 32
    for (int s = 0; s < NSTEP; s++) {
        CP_WAIT1();
        __syncthreads();
        if (s + 2 < NSTEP) gemm_issue_stage(Ablk, Wblk, sbase, s + 2, tid);
        else CP_COMMIT();   // keep group count advancing so WAIT1 stays exact

        const int buf = s % NST;
        const uint32_t* Asu = (const uint32_t*)smf + (size_t)buf * STAGE_FLOATS;
        const uint32_t* Bsu = Asu + BM * BKP;

        #pragma unroll
        for (int ks = 0; ks < 4; ks++) {
            const int kb = ks * 8;
            uint32_t af[4][4], bf[8][2];
            #pragma unroll
            for (int mt = 0; mt < 4; mt++) {
                int r0 = wM * 64 + mt * 16 + grp;
                af[mt][0] = Asu[r0       * BKP + kb + qd];
                af[mt][1] = Asu[(r0 + 8) * BKP + kb + qd];
                af[mt][2] = Asu[r0       * BKP + kb + qd + 4];
                af[mt][3] = Asu[(r0 + 8) * BKP + kb + qd + 4];
            }
            #pragma unroll
            for (int nt = 0; nt < 8; nt++) {
                int n0 = wN * 64 + nt * 8 + grp;
                bf[nt][0] = Bsu[n0 * BKP + kb + qd];
                bf[nt][1] = Bsu[n0 * BKP + kb + qd + 4];
            }
            #pragma unroll
            for (int mt = 0; mt < 4; mt++)
                #pragma unroll
                for (int nt = 0; nt < 8; nt++)
                    mma_tf32(acc[mt][nt], af[mt], bf[nt]);
        }
    }

    // Epilogue
    #pragma unroll
    for (int mt = 0; mt < 4; mt++) {
        #pragma unroll
        for (int nt = 0; nt < 8; nt++) {
            int m0 = bm * BM + wM * 64 + mt * 16 + grp;
            int n0 = bn * BN + wN * 64 + nt * 8 + qd * 2;
            float v0 = acc[mt][nt][0], v1 = acc[mt][nt][1];
            float v2 = acc[mt][nt][2], v3 = acc[mt][nt][3];
            if (EPI == 1) {
                v0 = 1.f / (1.f + __expf(-v0));
                v1 = 1.f / (1.f + __expf(-v1));
                v2 = 1.f / (1.f + __expf(-v2));
                v3 = 1.f / (1.f + __expf(-v3));
            }
            *(float2*)&Out[(size_t)m0 * Cc + n0]       = make_float2(v0, v1);
            *(float2*)&Out[(size_t)(m0 + 8) * Cc + n0] = make_float2(v2, v3);
        }
    }
}

// ===========================================================================
// WKV chunk-parallel scan
// ===========================================================================
__global__ void wkv_phase1(const float* __restrict__ K, const float* __restrict__ V,
                           const float* __restrict__ time_decay,
                           float* __restrict__ st_aa, float* __restrict__ st_bb,
                           float* __restrict__ st_pp) {
    int idx = blockIdx.x * blockDim.x + threadIdx.x;
    int bc = idx & (BC - 1);
    int ch = idx >> 13;
    int c  = bc & (Cc - 1);
    int b  = bc >> 10;
    float w = -__expf(time_decay[c]);

    float aa = 0.f, bb = 0.f, pp = -1e30f;
    size_t off = ((size_t)b * Tt + (size_t)ch * CHL) * Cc + c;
    for (int t = 0; t < CHL; t++) {
        float kt = K[off];
        float vt = V[off];
        float ww2 = w + pp;
        float p2  = fmaxf(ww2, kt);
        float e1b = __expf(ww2 - p2);
        float e2b = __expf(kt - p2);
        aa = aa * e1b + vt * e2b;
        bb = bb * e1b + e2b;
        pp = p2;
        off += Cc;
    }
    st_aa[idx] = aa; st_bb[idx] = bb; st_pp[idx] = pp;
}

__global__ void wkv_phase2(const float* __restrict__ time_decay,
                           const float* __restrict__ st_aa, const float* __restrict__ st_bb,
                           const float* __restrict__ st_pp,
                           float* __restrict__ in_aa, float* __restrict__ in_bb,
                           float* __restrict__ in_pp) {
    int bc = blockIdx.x * blockDim.x + threadIdx.x;
    int c  = bc & (Cc - 1);
    float w  = -__expf(time_decay[c]);
    float wL = w * (float)CHL;

    float aa = 0.f, bb = 0.f, pp = -1e30f;
    for (int ch = 0; ch < NCH; ch++) {
        int i = ch * BC + bc;
        in_aa[i] = aa; in_bb[i] = bb; in_pp[i] = pp;
        float la = st_aa[i], lb = st_bb[i], lp = st_pp[i];
        float pn   = fmaxf(pp + wL, lp);
        float e_in = __expf(pp + wL - pn);
        float e_lc = __expf(lp - pn);
        aa = aa * e_in + la * e_lc;
        bb = bb * e_in + lb * e_lc;
        pp = pn;
    }
}

__global__ void wkv_phase3(const float* __restrict__ K, const float* __restrict__ V,
                           const float* __restrict__ R, float* __restrict__ RY,
                           const float* __restrict__ time_decay,
                           const float* __restrict__ time_first,
                           const float* __restrict__ in_aa, const float* __restrict__ in_bb,
                           const float* __restrict__ in_pp) {
    int idx = blockIdx.x * blockDim.x + threadIdx.x;
    int bc = idx & (BC - 1);
    int ch = idx >> 13;
    int c  = bc & (Cc - 1);
    int b  = bc >> 10;
    float w = -__expf(time_decay[c]);
    float u = time_first[c];

    float aa = in_aa[idx], bb = in_bb[idx], pp = in_pp[idx];
    size_t off = ((size_t)b * Tt + (size_t)ch * CHL) * Cc + c;
    for (int t = 0; t < CHL; t++) {
        float kt = K[off];
        float vt = V[off];

        float ww = u + pp;
        float p  = fmaxf(ww, kt);
        float e1 = __expf(ww - p);
        float e2 = __expf(kt - p);
        float y  = (aa * e1 + vt * e2) / (bb * e1 + e2 + 1e-6f);
        RY[off] = rndtf32(y * R[off]);   // tf32-rounded: feeds the output GEMM

        float ww2 = w + pp;
        float p2  = fmaxf(ww2, kt);
        float e1b = __expf(ww2 - p2);
        float e2b = __expf(kt - p2);
        aa = aa * e1b + vt * e2b;
        bb = bb * e1b + e2b;
        pp = p2;
        off += Cc;
    }
}

// ===========================================================================
// Launch
// ===========================================================================
extern "C" void kernel_launch(void* const* d_in, const int* in_sizes, int n_in,
                              void* d_out, int out_size) {
    const float* x          = (const float*)d_in[0];
    const float* time_decay = (const float*)d_in[1];
    const float* time_first = (const float*)d_in[2];
    const float* tmk        = (const float*)d_in[3];
    const float* tmv        = (const float*)d_in[4];
    const float* tmr        = (const float*)d_in[5];
    const float* Wk         = (const float*)d_in[6];
    const float* Wv         = (const float*)d_in[7];
    const float* Wr         = (const float*)d_in[8];
    const float* Wo         = (const float*)d_in[9];
    float* out = (float*)d_out;

    float* scratch = nullptr;
    cudaGetSymbolAddress((void**)&scratch, g_scratch);
    float* g_xk = scratch + 0ull * NELEM;
    float* g_xv = scratch + 1ull * NELEM;
    float* g_xr = scratch + 2ull * NELEM;
    float* g_k  = scratch + 3ull * NELEM;
    float* g_v  = scratch + 4ull * NELEM;

    float* state = nullptr;
    cudaGetSymbolAddress((void**)&state, g_state);
    float* st_aa = state + 0ull * BC * NCH;
    float* st_bb = state + 1ull * BC * NCH;
    float* st_pp = state + 2ull * BC * NCH;
    float* in_aa = state + 3ull * BC * NCH;
    float* in_bb = state + 4ull * BC * NCH;
    float* in_pp = state + 5ull * BC * NCH;

    float* wr = nullptr;
    cudaGetSymbolAddress((void**)&wr, g_wr);
    float* rWk = wr + 0ull * 1024 * 1024;
    float* rWv = wr + 1ull * 1024 * 1024;
    float* rWr = wr + 2ull * 1024 * 1024;
    float* rWo = wr + 3ull * 1024 * 1024;

    cudaFuncSetAttribute(gemm_tc<0>, cudaFuncAttributeMaxDynamicSharedMemorySize, GEMM_SMEM);
    cudaFuncSetAttribute(gemm_tc<1>, cudaFuncAttributeMaxDynamicSharedMemorySize, GEMM_SMEM);

    // 0. round weights to tf32-representable fp32
    {
        int n4 = 1024 * 1024 / 4;
        round_tf32_kernel<<<n4 / 256, 256>>>((const float4*)Wk, (float4*)rWk, n4);
        round_tf32_kernel<<<n4 / 256, 256>>>((const float4*)Wv, (float4*)rWv, n4);
        round_tf32_kernel<<<n4 / 256, 256>>>((const float4*)Wr, (float4*)rWr, n4);
        round_tf32_kernel<<<n4 / 256, 256>>>((const float4*)Wo, (float4*)rWo, n4);
    }

    // 1. mix (tf32-rounded outputs)
    {
        int total4 = Bb * Tt * Cc / 4;
        mix_kernel<<<total4 / 256, 256>>>((const float4*)x,
                                          (const float4*)tmk, (const float4*)tmv,
                                          (const float4*)tmr,
                                          (float4*)g_xk, (float4*)g_xv, (float4*)g_xr);
    }

    dim3 grid(Cc / BN, (Bb * Tt) / BM);   // (8, 256)

    // 2-4. projections
    gemm_tc<0><<<grid, 128, GEMM_SMEM>>>(g_xk, rWk, g_k);
    gemm_tc<0><<<grid, 128, GEMM_SMEM>>>(g_xv, rWv, g_v);
    gemm_tc<1><<<grid, 128, GEMM_SMEM>>>(g_xr, rWr, g_xk);  // r -> g_xk

    // 5. chunk-parallel WKV; ry -> g_xv
    wkv_phase1<<<(BC * NCH) / 256, 256>>>(g_k, g_v, time_decay, st_aa, st_bb, st_pp);
    wkv_phase2<<<BC / 256, 256>>>(time_decay, st_aa, st_bb, st_pp, in_aa, in_bb, in_pp);
    wkv_phase3<<<(BC * NCH) / 256, 256>>>(g_k, g_v, g_xk, g_xv, time_decay, time_first,
                                          in_aa, in_bb, in_pp);

    // 6. out = ry @ Wo^T
    gemm_tc<0><<<grid, 128, GEMM_SMEM>>>(g_xv, rWo, out);
}

// round 5
// speedup vs baseline: 2.7511x; 1.0035x over previous
#include <cuda_runtime.h>
#include <cstdint>

#define Bb 8
#define Tt 4096
#define Cc 1024
#define NELEM (8u*4096u*1024u)
#define NCH 32
#define CHL 128
#define BC  (Bb*Cc)

__device__ float g_scratch[5ull * NELEM];
__device__ float g_state[6ull * BC * NCH];
__device__ float g_wr[4ull * 1024 * 1024];   // tf32-rounded weights

// ===========================================================================
// helpers
// ===========================================================================
__device__ __forceinline__ uint32_t smem_to_u32(const void* p) {
    uint32_t a;
    asm("{ .reg .u64 t; cvta.to.shared.u64 t, %1; cvt.u32.u64 %0, t; }"
        : "=r"(a) : "l"(p));
    return a;
}

__device__ __forceinline__ float rndtf32(float x) {
    uint32_t r;
    asm("cvt.rna.tf32.f32 %0, %1;" : "=r"(r) : "f"(x));
    return __uint_as_float(r);
}

__device__ __forceinline__ void mma_tf32(float c[4], const uint32_t a[4], const uint32_t b[2]) {
    asm volatile(
        "mma.sync.aligned.m16n8k8.row.col.f32.tf32.tf32.f32 "
        "{%0,%1,%2,%3}, {%4,%5,%6,%7}, {%8,%9}, {%0,%1,%2,%3};\n"
        : "+f"(c[0]), "+f"(c[1]), "+f"(c[2]), "+f"(c[3])
        : "r"(a[0]), "r"(a[1]), "r"(a[2]), "r"(a[3]), "r"(b[0]), "r"(b[1]));
}

__device__ __forceinline__ void cp_async16(uint32_t dst, const void* src) {
    asm volatile("cp.async.cg.shared.global [%0], [%1], 16;" :: "r"(dst), "l"(src));
}
#define CP_COMMIT() asm volatile("cp.async.commit_group;" ::: "memory")
#define CP_WAIT1()  asm volatile("cp.async.wait_group 1;" ::: "memory")

// ===========================================================================
// round all 4 weight matrices to tf32-representable fp32 (single launch)
// ===========================================================================
__global__ void round_w_kernel(const float4* __restrict__ w0, const float4* __restrict__ w1,
                               const float4* __restrict__ w2, const float4* __restrict__ w3,
                               float4* __restrict__ o0, float4* __restrict__ o1,
                               float4* __restrict__ o2, float4* __restrict__ o3) {
    int i = blockIdx.x * blockDim.x + threadIdx.x;   // 0 .. 1024*1024/4-1
    float4 a = w0[i], b = w1[i], c = w2[i], d = w3[i];
    o0[i] = make_float4(rndtf32(a.x), rndtf32(a.y), rndtf32(a.z), rndtf32(a.w));
    o1[i] = make_float4(rndtf32(b.x), rndtf32(b.y), rndtf32(b.z), rndtf32(b.w));
    o2[i] = make_float4(rndtf32(c.x), rndtf32(c.y), rndtf32(c.z), rndtf32(c.w));
    o3[i] = make_float4(rndtf32(d.x), rndtf32(d.y), rndtf32(d.z), rndtf32(d.w));
}

// ===========================================================================
// Mix kernel (tf32-rounded outputs)
// ===========================================================================
__global__ void mix_kernel(const float4* __restrict__ x4,
                           const float4* __restrict__ tmk4,
                           const float4* __restrict__ tmv4,
                           const float4* __restrict__ tmr4,
                           float4* __restrict__ xk4,
                           float4* __restrict__ xv4,
                           float4* __restrict__ xr4) {
    int i = blockIdx.x * blockDim.x + threadIdx.x;
    int c4 = i & (Cc/4 - 1);
    int bt = i >> 8;
    int t  = bt & (Tt - 1);
    float4 xc = x4[i];
    float4 xp = make_float4(0.f, 0.f, 0.f, 0.f);
    if (t != 0) xp = x4[i - Cc/4];
    float4 mk = tmk4[c4], mv = tmv4[c4], mr = tmr4[c4];
    float4 ok, ov, orr;
    ok.x = rndtf32(xc.x*mk.x + xp.x*(1.f-mk.x)); ok.y = rndtf32(xc.y*mk.y + xp.y*(1.f-mk.y));
    ok.z = rndtf32(xc.z*mk.z + xp.z*(1.f-mk.z)); ok.w = rndtf32(xc.w*mk.w + xp.w*(1.f-mk.w));
    ov.x = rndtf32(xc.x*mv.x + xp.x*(1.f-mv.x)); ov.y = rndtf32(xc.y*mv.y + xp.y*(1.f-mv.y));
    ov.z = rndtf32(xc.z*mv.z + xp.z*(1.f-mv.z)); ov.w = rndtf32(xc.w*mv.w + xp.w*(1.f-mv.w));
    orr.x = rndtf32(xc.x*mr.x + xp.x*(1.f-mr.x)); orr.y = rndtf32(xc.y*mr.y + xp.y*(1.f-mr.y));
    orr.z = rndtf32(xc.z*mr.z + xp.z*(1.f-mr.z)); orr.w = rndtf32(xc.w*mr.w + xp.w*(1.f-mr.w));
    xk4[i] = ok; xv4[i] = ov; xr4[i] = orr;
}

// ===========================================================================
// TF32 GEMM: Out[m,n] = sum_k A[m,k]*W[n,k]
// CTA 128x128, 4 warps (warp tile 64x64), BK=32, 3-stage cp.async,
// register-double-buffered fragments (software pipeline inside each stage).
// ===========================================================================
#define BM 128
#define BN 128
#define BKF 32
#define BKP 36
#define NST 3
#define STAGE_FLOATS ((BM + BN) * BKP)      // 9216 floats
#define GEMM_SMEM (NST * STAGE_FLOATS * 4)  // 110592 B -> 2 CTAs/SM

__device__ __forceinline__ void gemm_issue_stage(
    const float* __restrict__ Ablk, const float* __restrict__ Wblk,
    uint32_t sbase, int s, int tid) {
    int buf = s % NST;
    uint32_t sA = sbase + (uint32_t)buf * (STAGE_FLOATS * 4);
    uint32_t sB = sA + BM * BKP * 4;
    int k0 = s * BKF;
    #pragma unroll
    for (int i = 0; i < 8; i++) {
        int idx = i * 128 + tid;
        int row = idx >> 3;
        int c4  = (idx & 7) * 4;
        cp_async16(sA + (uint32_t)(row * BKP + c4) * 4, Ablk + (size_t)row * Cc + k0 + c4);
        cp_async16(sB + (uint32_t)(row * BKP + c4) * 4, Wblk + (size_t)row * Cc + k0 + c4);
    }
    CP_COMMIT();
}

__device__ __forceinline__ void load_frags(
    const uint32_t* __restrict__ Asu, const uint32_t* __restrict__ Bsu,
    int ks, int wM, int wN, int grp, int qd,
    uint32_t af[4][4], uint32_t bf[8][2]) {
    const int kb = ks * 8;
    #pragma unroll
    for (int mt = 0; mt < 4; mt++) {
        int r0 = wM * 64 + mt * 16 + grp;
        af[mt][0] = Asu[r0       * BKP + kb + qd];
        af[mt][1] = Asu[(r0 + 8) * BKP + kb + qd];
        af[mt][2] = Asu[r0       * BKP + kb + qd + 4];
        af[mt][3] = Asu[(r0 + 8) * BKP + kb + qd + 4];
    }
    #pragma unroll
    for (int nt = 0; nt < 8; nt++) {
        int n0 = wN * 64 + nt * 8 + grp;
        bf[nt][0] = Bsu[n0 * BKP + kb + qd];
        bf[nt][1] = Bsu[n0 * BKP + kb + qd + 4];
    }
}

template <int EPI>
__global__ __launch_bounds__(128, 2)
void gemm_tc(const float* __restrict__ A, const float* __restrict__ W,
             float* __restrict__ Out) {
    extern __shared__ float smf[];
    const uint32_t sbase = smem_to_u32(smf);
    const int tid  = threadIdx.x;
    const int warp = tid >> 5, lane = tid & 31;
    const int wM = warp >> 1, wN = warp & 1;
    const int grp = lane >> 2, qd = lane & 3;
    const int bn = blockIdx.x, bm = blockIdx.y;

    const float* Ablk = A + (size_t)bm * BM * Cc;
    const float* Wblk = W + (size_t)bn * BN * Cc;

    float acc[4][8][4];
    #pragma unroll
    for (int mt = 0; mt < 4; mt++)
        #pragma unroll
        for (int nt = 0; nt < 8; nt++)
            #pragma unroll
            for (int j = 0; j < 4; j++) acc[mt][nt][j] = 0.f;

    gemm_issue_stage(Ablk, Wblk, sbase, 0, tid);
    gemm_issue_stage(Ablk, Wblk, sbase, 1, tid);

    uint32_t af[2][4][4], bf[2][8][2];

    const int NSTEP = Cc / BKF;   // 32
    for (int s = 0; s < NSTEP; s++) {
        CP_WAIT1();
        __syncthreads();
        if (s + 2 < NSTEP) gemm_issue_stage(Ablk, Wblk, sbase, s + 2, tid);
        else CP_COMMIT();   // keep group count advancing so WAIT1 stays exact

        const int buf = s % NST;
        const uint32_t* Asu = (const uint32_t*)smf + (size_t)buf * STAGE_FLOATS;
        const uint32_t* Bsu = Asu + BM * BKP;

        // software-pipelined fragment loads: load ks+1 while issuing mma(ks)
        load_frags(Asu, Bsu, 0, wM, wN, grp, qd, af[0], bf[0]);
        #pragma unroll
        for (int ks = 0; ks < 4; ks++) {
            const int cur = ks & 1;
            if (ks < 3)
                load_frags(Asu, Bsu, ks + 1, wM, wN, grp, qd, af[cur ^ 1], bf[cur ^ 1]);
            #pragma unroll
            for (int mt = 0; mt < 4; mt++)
                #pragma unroll
                for (int nt = 0; nt < 8; nt++)
                    mma_tf32(acc[mt][nt], af[cur][mt], bf[cur][nt]);
        }
    }

    // Epilogue
    #pragma unroll
    for (int mt = 0; mt < 4; mt++) {
        #pragma unroll
        for (int nt = 0; nt < 8; nt++) {
            int m0 = bm * BM + wM * 64 + mt * 16 + grp;
            int n0 = bn * BN + wN * 64 + nt * 8 + qd * 2;
            float v0 = acc[mt][nt][0], v1 = acc[mt][nt][1];
            float v2 = acc[mt][nt][2], v3 = acc[mt][nt][3];
            if (EPI == 1) {
                v0 = 1.f / (1.f + __expf(-v0));
                v1 = 1.f / (1.f + __expf(-v1));
                v2 = 1.f / (1.f + __expf(-v2));
                v3 = 1.f / (1.f + __expf(-v3));
            }
            *(float2*)&Out[(size_t)m0 * Cc + n0]       = make_float2(v0, v1);
            *(float2*)&Out[(size_t)(m0 + 8) * Cc + n0] = make_float2(v2, v3);
        }
    }
}

// ===========================================================================
// WKV chunk-parallel scan
// ===========================================================================
__global__ void wkv_phase1(const float* __restrict__ K, const float* __restrict__ V,
                           const float* __restrict__ time_decay,
                           float* __restrict__ st_aa, float* __restrict__ st_bb,
                           float* __restrict__ st_pp) {
    int idx = blockIdx.x * blockDim.x + threadIdx.x;
    int bc = idx & (BC - 1);
    int ch = idx >> 13;
    int c  = bc & (Cc - 1);
    int b  = bc >> 10;
    float w = -__expf(time_decay[c]);

    float aa = 0.f, bb = 0.f, pp = -1e30f;
    size_t off = ((size_t)b * Tt + (size_t)ch * CHL) * Cc + c;
    for (int t = 0; t < CHL; t++) {
        float kt = K[off];
        float vt = V[off];
        float ww2 = w + pp;
        float p2  = fmaxf(ww2, kt);
        float e1b = __expf(ww2 - p2);
        float e2b = __expf(kt - p2);
        aa = aa * e1b + vt * e2b;
        bb = bb * e1b + e2b;
        pp = p2;
        off += Cc;
    }
    st_aa[idx] = aa; st_bb[idx] = bb; st_pp[idx] = pp;
}

__global__ void wkv_phase2(const float* __restrict__ time_decay,
                           const float* __restrict__ st_aa, const float* __restrict__ st_bb,
                           const float* __restrict__ st_pp,
                           float* __restrict__ in_aa, float* __restrict__ in_bb,
                           float* __restrict__ in_pp) {
    int bc = blockIdx.x * blockDim.x + threadIdx.x;
    int c  = bc & (Cc - 1);
    float w  = -__expf(time_decay[c]);
    float wL = w * (float)CHL;

    float aa = 0.f, bb = 0.f, pp = -1e30f;
    for (int ch = 0; ch < NCH; ch++) {
        int i = ch * BC + bc;
        in_aa[i] = aa; in_bb[i] = bb; in_pp[i] = pp;
        float la = st_aa[i], lb = st_bb[i], lp = st_pp[i];
        float pn   = fmaxf(pp + wL, lp);
        float e_in = __expf(pp + wL - pn);
        float e_lc = __expf(lp - pn);
        aa = aa * e_in + la * e_lc;
        bb = bb * e_in + lb * e_lc;
        pp = pn;
    }
}

__global__ void wkv_phase3(const float* __restrict__ K, const float* __restrict__ V,
                           const float* __restrict__ R, float* __restrict__ RY,
                           const float* __restrict__ time_decay,
                           const float* __restrict__ time_first,
                           const float* __restrict__ in_aa, const float* __restrict__ in_bb,
                           const float* __restrict__ in_pp) {
    int idx = blockIdx.x * blockDim.x + threadIdx.x;
    int bc = idx & (BC - 1);
    int ch = idx >> 13;
    int c  = bc & (Cc - 1);
    int b  = bc >> 10;
    float w = -__expf(time_decay[c]);
    float u = time_first[c];

    float aa = in_aa[idx], bb = in_bb[idx], pp = in_pp[idx];
    size_t off = ((size_t)b * Tt + (size_t)ch * CHL) * Cc + c;
    for (int t = 0; t < CHL; t++) {
        float kt = K[off];
        float vt = V[off];

        float ww = u + pp;
        float p  = fmaxf(ww, kt);
        float e1 = __expf(ww - p);
        float e2 = __expf(kt - p);
        float y  = (aa * e1 + vt * e2) / (bb * e1 + e2 + 1e-6f);
        RY[off] = rndtf32(y * R[off]);

        float ww2 = w + pp;
        float p2  = fmaxf(ww2, kt);
        float e1b = __expf(ww2 - p2);
        float e2b = __expf(kt - p2);
        aa = aa * e1b + vt * e2b;
        bb = bb * e1b + e2b;
        pp = p2;
        off += Cc;
    }
}

// ===========================================================================
// Launch
// ===========================================================================
extern "C" void kernel_launch(void* const* d_in, const int* in_sizes, int n_in,
                              void* d_out, int out_size) {
    const float* x          = (const float*)d_in[0];
    const float* time_decay = (const float*)d_in[1];
    const float* time_first = (const float*)d_in[2];
    const float* tmk        = (const float*)d_in[3];
    const float* tmv        = (const float*)d_in[4];
    const float* tmr        = (const float*)d_in[5];
    const float* Wk         = (const float*)d_in[6];
    const float* Wv         = (const float*)d_in[7];
    const float* Wr         = (const float*)d_in[8];
    const float* Wo         = (const float*)d_in[9];
    float* out = (float*)d_out;

    float* scratch = nullptr;
    cudaGetSymbolAddress((void**)&scratch, g_scratch);
    float* g_xk = scratch + 0ull * NELEM;
    float* g_xv = scratch + 1ull * NELEM;
    float* g_xr = scratch + 2ull * NELEM;
    float* g_k  = scratch + 3ull * NELEM;
    float* g_v  = scratch + 4ull * NELEM;

    float* state = nullptr;
    cudaGetSymbolAddress((void**)&state, g_state);
    float* st_aa = state + 0ull * BC * NCH;
    float* st_bb = state + 1ull * BC * NCH;
    float* st_pp = state + 2ull * BC * NCH;
    float* in_aa = state + 3ull * BC * NCH;
    float* in_bb = state + 4ull * BC * NCH;
    float* in_pp = state + 5ull * BC * NCH;

    float* wr = nullptr;
    cudaGetSymbolAddress((void**)&wr, g_wr);
    float* rWk = wr + 0ull * 1024 * 1024;
    float* rWv = wr + 1ull * 1024 * 1024;
    float* rWr = wr + 2ull * 1024 * 1024;
    float* rWo = wr + 3ull * 1024 * 1024;

    cudaFuncSetAttribute(gemm_tc<0>, cudaFuncAttributeMaxDynamicSharedMemorySize, GEMM_SMEM);
    cudaFuncSetAttribute(gemm_tc<1>, cudaFuncAttributeMaxDynamicSharedMemorySize, GEMM_SMEM);

    // 0. round weights to tf32-representable fp32 (one launch)
    {
        int n4 = 1024 * 1024 / 4;
        round_w_kernel<<<n4 / 256, 256>>>(
            (const float4*)Wk, (const float4*)Wv, (const float4*)Wr, (const float4*)Wo,
            (float4*)rWk, (float4*)rWv, (float4*)rWr, (float4*)rWo);
    }

    // 1. mix (tf32-rounded outputs)
    {
        int total4 = Bb * Tt * Cc / 4;
        mix_kernel<<<total4 / 256, 256>>>((const float4*)x,
                                          (const float4*)tmk, (const float4*)tmv,
                                          (const float4*)tmr,
                                          (float4*)g_xk, (float4*)g_xv, (float4*)g_xr);
    }

    dim3 grid(Cc / BN, (Bb * Tt) / BM);   // (8, 256)

    // 2-4. projections
    gemm_tc<0><<<grid, 128, GEMM_SMEM>>>(g_xk, rWk, g_k);
    gemm_tc<0><<<grid, 128, GEMM_SMEM>>>(g_xv, rWv, g_v);
    gemm_tc<1><<<grid, 128, GEMM_SMEM>>>(g_xr, rWr, g_xk);  // r -> g_xk

    // 5. chunk-parallel WKV; ry -> g_xv
    wkv_phase1<<<(BC * NCH) / 256, 256>>>(g_k, g_v, time_decay, st_aa, st_bb, st_pp);
    wkv_phase2<<<BC / 256, 256>>>(time_decay, st_aa, st_bb, st_pp, in_aa, in_bb, in_pp);
    wkv_phase3<<<(BC * NCH) / 256, 256>>>(g_k, g_v, g_xk, g_xv, time_decay, time_first,
                                          in_aa, in_bb, in_pp);

    // 6. out = ry @ Wo^T
    gemm_tc<0><<<grid, 128, GEMM_SMEM>>>(g_xv, rWo, out);
}